// round 1
// baseline (speedup 1.0000x reference)
#include <cuda_runtime.h>

// SplineLoss on GB300: the reference samples the spline only at integer knot
// times (t = 0,10,...,1020), where dx == 0.0 exactly, so every moment term
// vanishes and the loss reduces EXACTLY to a strided MSE:
//   mean over t in {0,10,...,1020}, b, d of (true[b,t,d] - pred[b,t,d])^2
// Layout: frames are (B,T,D) row-major; each sampled (b,t) row is a
// contiguous 64-float (256 B) run -> fully coalesced float4 loads.

#define B_ 128
#define T_ 1024
#define D_ 64
#define S_ 103            // number of sample times: 0,10,...,1020
#define STEP_ 10
#define D4_ (D_ / 4)      // 16 float4 per row
#define TOTAL4_ (B_ * S_ * D4_)          // 210944 float4 pairs
#define COUNT_ ((float)(B_ * S_ * D_))   // 843776 elements in the mean

constexpr int NBLK = 512;
constexpr int NTHR = 256;

__device__ float g_partials[NBLK];

__global__ __launch_bounds__(NTHR) void spline_mse_partial(
    const float* __restrict__ yt, const float* __restrict__ yp)
{
    float acc = 0.0f;
    const float4* __restrict__ a4 = (const float4*)yt;
    const float4* __restrict__ b4 = (const float4*)yp;

    for (int i = blockIdx.x * NTHR + threadIdx.x; i < TOTAL4_; i += NBLK * NTHR) {
        int d4   = i % D4_;
        int rest = i / D4_;
        int s    = rest % S_;
        int b    = rest / S_;
        int addr = (b * T_ + s * STEP_) * D4_ + d4;   // < 2^21, fits int
        float4 va = __ldg(&a4[addr]);
        float4 vb = __ldg(&b4[addr]);
        float e0 = va.x - vb.x;
        float e1 = va.y - vb.y;
        float e2 = va.z - vb.z;
        float e3 = va.w - vb.w;
        acc = fmaf(e0, e0, acc);
        acc = fmaf(e1, e1, acc);
        acc = fmaf(e2, e2, acc);
        acc = fmaf(e3, e3, acc);
    }

    // warp reduce
    #pragma unroll
    for (int o = 16; o > 0; o >>= 1)
        acc += __shfl_down_sync(0xffffffffu, acc, o);

    __shared__ float sh[NTHR / 32];
    if ((threadIdx.x & 31) == 0) sh[threadIdx.x >> 5] = acc;
    __syncthreads();

    if (threadIdx.x < 32) {
        float v = (threadIdx.x < NTHR / 32) ? sh[threadIdx.x] : 0.0f;
        #pragma unroll
        for (int o = 16; o > 0; o >>= 1)
            v += __shfl_down_sync(0xffffffffu, v, o);
        if (threadIdx.x == 0) g_partials[blockIdx.x] = v;
    }
}

__global__ __launch_bounds__(NBLK) void spline_mse_finalize(float* __restrict__ out)
{
    float acc = g_partials[threadIdx.x];   // one block of NBLK threads

    #pragma unroll
    for (int o = 16; o > 0; o >>= 1)
        acc += __shfl_down_sync(0xffffffffu, acc, o);

    __shared__ float sh[NBLK / 32];
    if ((threadIdx.x & 31) == 0) sh[threadIdx.x >> 5] = acc;
    __syncthreads();

    if (threadIdx.x < 32) {
        float v = (threadIdx.x < NBLK / 32) ? sh[threadIdx.x] : 0.0f;
        #pragma unroll
        for (int o = 16; o > 0; o >>= 1)
            v += __shfl_down_sync(0xffffffffu, v, o);
        if (threadIdx.x == 0) out[0] = v / COUNT_;
    }
}

extern "C" void kernel_launch(void* const* d_in, const int* in_sizes, int n_in,
                              void* d_out, int out_size)
{
    const float* yt = (const float*)d_in[0];   // true_frames
    const float* yp = (const float*)d_in[1];   // predicted_frames
    float* out = (float*)d_out;

    spline_mse_partial<<<NBLK, NTHR>>>(yt, yp);
    spline_mse_finalize<<<1, NBLK>>>(out);
}